// round 14
// baseline (speedup 1.0000x reference)
#include <cuda_runtime.h>

#define Bsz   16
#define Lseq  2048
#define Hdim  512
#define N2    32
#define Tc    32
#define NC    (Lseq / Tc)   /* 64 chunks */
#define HG    8
#define LPAD  2052          /* per-head time-contiguous stride (mult of 4) */
#define NCW   8             /* chunks per warp within a stream */

/* ---- precomputed per-mode tables ---- */
__device__ float4 g_AB[Hdim][N2];        /* (dtA.re, dtA.im, dtB.re, dtB.im)      */
__device__ float2 g_Q0[Hdim][N2];        /* 2*C*dtA                               */
__device__ float2 g_AT[Hdim][N2];        /* dtA^32                                */
__device__ float2 g_AT8[Hdim][N2];       /* dtA^256 (8-chunk block aggregate)     */
__device__ float  g_Vr[Hdim][N2][Tc];    /* Re(dtA^t)                             */
__device__ float  g_Vin[Hdim][N2][Tc];   /* -Im(dtA^t)                            */
__device__ float  g_K[Hdim][Tc];         /* K[j] = 2*Re(sum_n C*dtB*dtA^j)        */

__device__ __forceinline__ float2 cmul(float2 a, float2 b) {
    return make_float2(fmaf(a.x, b.x, -a.y * b.y), fmaf(a.x, b.y, a.y * b.x));
}

/* 8 heads per block, one warp per head; smem-transpose tap reduction */
__global__ void s4d_precompute(const float* __restrict__ log_dt,
                               const float* __restrict__ B_re,
                               const float* __restrict__ B_im,
                               const float* __restrict__ Cmat,
                               const float* __restrict__ A_real,
                               const float* __restrict__ A_imag)
{
    __shared__ float tk[8][Tc * 33];     /* per-warp [j][n] transpose pad */
    const int wid = threadIdx.x >> 5;
    const int n   = threadIdx.x & 31;    /* one mode per lane */
    const int h   = blockIdx.x * 8 + wid;
    const int idx = h * N2 + n;

    float dt  = expf(log_dt[h]);
    float Are = -expf(A_real[idx]) - 1e-6f;
    float Aim = A_imag[idx];

    float2 num = make_float2(1.f + 0.5f * dt * Are, 0.5f * dt * Aim);
    float2 den = make_float2(1.f + 1e-6f - 0.5f * dt * Are, -0.5f * dt * Aim);
    float  inv = 1.f / (den.x * den.x + den.y * den.y);
    float2 dtA = make_float2((num.x * den.x + num.y * den.y) * inv,
                             (num.y * den.x - num.x * den.y) * inv);
    float2 Bc  = make_float2(dt * B_re[idx], dt * B_im[idx]);
    float2 dtB = make_float2((Bc.x * den.x + Bc.y * den.y) * inv,
                             (Bc.y * den.x - Bc.x * den.y) * inv);
    float  Cv  = Cmat[idx];

    g_AB[h][n] = make_float4(dtA.x, dtA.y, dtB.x, dtB.y);
    g_Q0[h][n] = make_float2(2.f * Cv * dtA.x, 2.f * Cv * dtA.y);

    /* dtA^32 / dtA^256 by squaring */
    float2 a = dtA;
    #pragma unroll
    for (int s = 0; s < 5; ++s) a = cmul(a, a);
    g_AT[h][n] = a;
    float2 a8 = a;
    #pragma unroll
    for (int s = 0; s < 3; ++s) a8 = cmul(a8, a8);
    g_AT8[h][n] = a8;

    /* Vandermonde planes */
    float2 v = make_float2(1.f, 0.f);
    for (int t = 0; t < Tc; ++t) {
        g_Vr [h][n][t] =  v.x;
        g_Vin[h][n][t] = -v.y;
        v = cmul(v, dtA);
    }

    /* Toeplitz taps via smem transpose (no per-step shuffle reduce) */
    float2 ck = make_float2(Cv * dtB.x, Cv * dtB.y);
    for (int j = 0; j < Tc; ++j) {
        tk[wid][j * 33 + n] = ck.x;
        ck = cmul(ck, dtA);
    }
    __syncwarp();
    {
        int j = n;                       /* lane -> tap index */
        float s = 0.f;
        #pragma unroll 8
        for (int m = 0; m < N2; ++m) s += tk[wid][j * 33 + m];
        g_K[h][j] = 2.f * s;
    }
}

/* chunk projections for 4 chunks (bases b0..b3), lane = mode. */
__device__ __forceinline__ void proj4(const float* __restrict__ b0,
                                      const float* __restrict__ b1,
                                      const float* __restrict__ b2,
                                      const float* __restrict__ b3,
                                      float axr, float axi, float2 dtB,
                                      float2& o0, float2& o1, float2& o2, float2& o3)
{
    float pr = dtB.x, pi = dtB.y;
    float w0r = 0, w0i = 0, w1r = 0, w1i = 0;
    float w2r = 0, w2i = 0, w3r = 0, w3i = 0;
    #pragma unroll 2
    for (int tg = Tc - 4; tg >= 0; tg -= 4) {
        float4 a0 = *(const float4*)(b0 + tg);
        float4 a1 = *(const float4*)(b1 + tg);
        float4 a2 = *(const float4*)(b2 + tg);
        float4 a3 = *(const float4*)(b3 + tg);
        w0r = fmaf(pr, a0.w, w0r); w0i = fmaf(pi, a0.w, w0i);
        w1r = fmaf(pr, a1.w, w1r); w1i = fmaf(pi, a1.w, w1i);
        w2r = fmaf(pr, a2.w, w2r); w2i = fmaf(pi, a2.w, w2i);
        w3r = fmaf(pr, a3.w, w3r); w3i = fmaf(pi, a3.w, w3i);
        { float t_ = fmaf(pr, axr, -pi * axi); pi = fmaf(pr, axi, pi * axr); pr = t_; }
        w0r = fmaf(pr, a0.z, w0r); w0i = fmaf(pi, a0.z, w0i);
        w1r = fmaf(pr, a1.z, w1r); w1i = fmaf(pi, a1.z, w1i);
        w2r = fmaf(pr, a2.z, w2r); w2i = fmaf(pi, a2.z, w2i);
        w3r = fmaf(pr, a3.z, w3r); w3i = fmaf(pi, a3.z, w3i);
        { float t_ = fmaf(pr, axr, -pi * axi); pi = fmaf(pr, axi, pi * axr); pr = t_; }
        w0r = fmaf(pr, a0.y, w0r); w0i = fmaf(pi, a0.y, w0i);
        w1r = fmaf(pr, a1.y, w1r); w1i = fmaf(pi, a1.y, w1i);
        w2r = fmaf(pr, a2.y, w2r); w2i = fmaf(pi, a2.y, w2i);
        w3r = fmaf(pr, a3.y, w3r); w3i = fmaf(pi, a3.y, w3i);
        { float t_ = fmaf(pr, axr, -pi * axi); pi = fmaf(pr, axi, pi * axr); pr = t_; }
        w0r = fmaf(pr, a0.x, w0r); w0i = fmaf(pi, a0.x, w0i);
        w1r = fmaf(pr, a1.x, w1r); w1i = fmaf(pi, a1.x, w1i);
        w2r = fmaf(pr, a2.x, w2r); w2i = fmaf(pi, a2.x, w2i);
        w3r = fmaf(pr, a3.x, w3r); w3i = fmaf(pi, a3.x, w3i);
        { float t_ = fmaf(pr, axr, -pi * axi); pi = fmaf(pr, axi, pi * axr); pr = t_; }
    }
    o0 = make_float2(w0r, w0i); o1 = make_float2(w1r, w1i);
    o2 = make_float2(w2r, w2i); o3 = make_float2(w3r, w3i);
}

/* smem: u 65664B + ws 32KB + bs (double-buffered, 2 streams) 8KB + Kw 2KB */
#define SMEM_BYTES (HG * LPAD * 4 + 2 * NC * N2 * 8 + 4 * NCW * N2 * 8 + 16 * Tc * 4)

#define STREAM_BAR(id) asm volatile("bar.sync %0, 256;" :: "r"(id) : "memory")

__global__ void __launch_bounds__(512, 2)
s4d_main(const float* __restrict__ u,
         const float* __restrict__ Dptr,
         float* __restrict__ out)
{
    extern __shared__ float sm[];
    float*  u_s = sm;                                   /* [hh][l], stride LPAD   */
    float2* ws  = (float2*)(sm + HG * LPAD);            /* [sid][chunk][mode] x'  */
    float2* bs  = ws + 2 * NC * N2;                     /* [sid][buf][wl][mode]   */
    float*  Kw  = (float*)(bs + 4 * NCW * N2);          /* [warp][32] taps        */

    const int b    = blockIdx.y;
    const int h0   = blockIdx.x * HG;
    const int tid  = threadIdx.x;
    const int warp = tid >> 5;
    const int lane = tid & 31;
    const int sid  = warp >> 3;       /* stream 0/1 */
    const int wl   = warp & 7;        /* warp within stream */
    const int barid = 1 + sid;
    const float Dv = *Dptr;

    float2* wsS = ws + sid * (NC * N2);
    float*  KsW = Kw + warp * Tc;

    /* ---- vectorized coalesced load -> per-head contiguous smem ---- */
    {
        const float4* ub4 = (const float4*)(u + (size_t)b * Lseq * Hdim + h0);
        #pragma unroll
        for (int it = 0; it < 8; ++it) {
            int f  = it * 512 + tid;          /* [0, 4096) */
            int l  = f >> 1;
            int hg = f & 1;
            float4 v = ub4[(size_t)l * (Hdim / 4) + hg];
            float* dst = u_s + (hg * 4) * LPAD + l;
            dst[0]        = v.x;
            dst[LPAD]     = v.y;
            dst[2 * LPAD] = v.z;
            dst[3 * LPAD] = v.w;
        }
    }
    __syncthreads();

    for (int ih = 0; ih < 4; ++ih) {
        const int hh = 2 * ih + sid;
        const int h  = h0 + hh;
        const float* uh = u_s + hh * LPAD;
        float2* bsB = bs + ((sid << 1) | (ih & 1)) * (NCW * N2);  /* dbl-buffered */

        KsW[lane] = g_K[h][lane];   /* per-warp taps; syncwarp before use below */

        /* ===== pass 1: 8 chunk projections per warp, kept in registers ===== */
        float4 ab = g_AB[h][lane];
        float2 dtB = make_float2(ab.z, ab.w);
        float2 w0, w1, w2, w3, w4, w5, w6, w7;
        {
            const float* cb = uh + (NCW * wl) * Tc;
            proj4(cb,          cb + Tc,     cb + 2 * Tc, cb + 3 * Tc,
                  ab.x, ab.y, dtB, w0, w1, w2, w3);
            proj4(cb + 4 * Tc, cb + 5 * Tc, cb + 6 * Tc, cb + 7 * Tc,
                  ab.x, ab.y, dtB, w4, w5, w6, w7);
        }

        /* ===== block aggregate S = sum AT^{7-j} w_j (Horner) -> bsB ===== */
        const float2 AT = g_AT[h][lane];
        {
            float sr = w0.x, si = w0.y;
            #define HSTEP(W) { float nr = fmaf(AT.x, sr, fmaf(-AT.y, si, (W).x)); \
                               float ni = fmaf(AT.x, si, fmaf( AT.y, sr, (W).y)); \
                               sr = nr; si = ni; }
            HSTEP(w1) HSTEP(w2) HSTEP(w3) HSTEP(w4) HSTEP(w5) HSTEP(w6) HSTEP(w7)
            #undef HSTEP
            bsB[wl * N2 + lane] = make_float2(sr, si);
        }
        STREAM_BAR(barid);   /* the ONLY cross-warp sync per head */

        /* ===== redundant per-warp scan of block aggregates + local expand ===== */
        {
            float2 A8 = g_AT8[h][lane];
            float2 Q0 = g_Q0[h][lane];
            float xr = 0.f, xi = 0.f, kr = 0.f, ki = 0.f;
            #pragma unroll
            for (int k = 0; k < NCW; ++k) {
                if (k == wl) { kr = xr; ki = xi; }   /* keep state entering own block */
                float2 S = bsB[k * N2 + lane];
                float nr = fmaf(A8.x, xr, fmaf(-A8.y, xi, S.x));
                float ni = fmaf(A8.x, xi, fmaf( A8.y, xr, S.y));
                xr = nr; xi = ni;
            }
            xr = kr; xi = ki;
            /* expand within own block; write x' = Q0 * x_entry (own warp range) */
            #define XSTEP(j, W) { \
                wsS[(NCW * wl + (j)) * N2 + lane] = \
                    make_float2(fmaf(Q0.x, xr, -Q0.y * xi), fmaf(Q0.x, xi, Q0.y * xr)); \
                float nr = fmaf(AT.x, xr, fmaf(-AT.y, xi, (W).x)); \
                float ni = fmaf(AT.x, xi, fmaf( AT.y, xr, (W).y)); \
                xr = nr; xi = ni; }
            XSTEP(0, w0) XSTEP(1, w1) XSTEP(2, w2) XSTEP(3, w3)
            XSTEP(4, w4) XSTEP(5, w5) XSTEP(6, w6) XSTEP(7, w7)
            #undef XSTEP
        }
        __syncwarp();   /* wsS + KsW writes visible across own warp's lanes */

        /* ===== pass 3: corr (V loaded once, 8 accumulators) + Toeplitz +
                 D*u + GELU.  lane = (cl, tb); chunks A = 8wl+cl, B = 8wl+4+cl ===== */
        {
            const int cl = lane >> 3, tb = lane & 7, t0 = tb << 2;
            const int chunkA = NCW * wl + cl;
            const int chunkB = NCW * wl + 4 + cl;

            float yA0 = 0.f, yA1 = 0.f, yA2 = 0.f, yA3 = 0.f;
            float yB0 = 0.f, yB1 = 0.f, yB2 = 0.f, yB3 = 0.f;

            /* --- inter-chunk correction: each V load feeds 8 accumulators --- */
            {
                const float4* Vr4 = (const float4*)&g_Vr [h][0][0];
                const float4* Vi4 = (const float4*)&g_Vin[h][0][0];
                const float4* xs4 = (const float4*)wsS;
                const int xbA = chunkA * (N2 / 2);
                const int xbB = chunkB * (N2 / 2);
                #pragma unroll 4
                for (int n2 = 0; n2 < N2; n2 += 2) {
                    float4 vr0 = Vr4[ n2      * 8 + tb];
                    float4 vi0 = Vi4[ n2      * 8 + tb];
                    float4 vr1 = Vr4[(n2 + 1) * 8 + tb];
                    float4 vi1 = Vi4[(n2 + 1) * 8 + tb];
                    float4 xa  = xs4[xbA + (n2 >> 1)];
                    float4 xb  = xs4[xbB + (n2 >> 1)];

                    yA0 = fmaf(xa.x, vr0.x, yA0); yA0 = fmaf(xa.y, vi0.x, yA0);
                    yA1 = fmaf(xa.x, vr0.y, yA1); yA1 = fmaf(xa.y, vi0.y, yA1);
                    yA2 = fmaf(xa.x, vr0.z, yA2); yA2 = fmaf(xa.y, vi0.z, yA2);
                    yA3 = fmaf(xa.x, vr0.w, yA3); yA3 = fmaf(xa.y, vi0.w, yA3);
                    yA0 = fmaf(xa.z, vr1.x, yA0); yA0 = fmaf(xa.w, vi1.x, yA0);
                    yA1 = fmaf(xa.z, vr1.y, yA1); yA1 = fmaf(xa.w, vi1.y, yA1);
                    yA2 = fmaf(xa.z, vr1.z, yA2); yA2 = fmaf(xa.w, vi1.z, yA2);
                    yA3 = fmaf(xa.z, vr1.w, yA3); yA3 = fmaf(xa.w, vi1.w, yA3);

                    yB0 = fmaf(xb.x, vr0.x, yB0); yB0 = fmaf(xb.y, vi0.x, yB0);
                    yB1 = fmaf(xb.x, vr0.y, yB1); yB1 = fmaf(xb.y, vi0.y, yB1);
                    yB2 = fmaf(xb.x, vr0.z, yB2); yB2 = fmaf(xb.y, vi0.z, yB2);
                    yB3 = fmaf(xb.x, vr0.w, yB3); yB3 = fmaf(xb.y, vi0.w, yB3);
                    yB0 = fmaf(xb.z, vr1.x, yB0); yB0 = fmaf(xb.w, vi1.x, yB0);
                    yB1 = fmaf(xb.z, vr1.y, yB1); yB1 = fmaf(xb.w, vi1.y, yB1);
                    yB2 = fmaf(xb.z, vr1.z, yB2); yB2 = fmaf(xb.w, vi1.z, yB2);
                    yB3 = fmaf(xb.z, vr1.w, yB3); yB3 = fmaf(xb.w, vi1.w, yB3);
                }
            }

            /* --- intra-chunk Toeplitz + epilogue, per rep (sequential) --- */
            const float4* Ks4 = (const float4*)KsW;
            const float is2 = 0.70710678118654752440f;

            #pragma unroll
            for (int rep = 0; rep < 2; ++rep) {
                const int chunk = (rep == 0) ? chunkA : chunkB;
                const float* uc = uh + chunk * Tc;
                float y0 = (rep == 0) ? yA0 : yB0;
                float y1 = (rep == 0) ? yA1 : yB1;
                float y2 = (rep == 0) ? yA2 : yB2;
                float y3 = (rep == 0) ? yA3 : yB3;

                float4 wc = *(const float4*)(uc + t0);
                const float4 uo = wc;
                #pragma unroll
                for (int jb = 0; jb < Tc; jb += 4) {
                    const int idx = t0 - jb - 4;
                    float4 wlq;
                    if (idx >= 0) wlq = *(const float4*)(uc + idx);
                    else          wlq = make_float4(0.f, 0.f, 0.f, 0.f);
                    float4 k4 = Ks4[jb >> 2];
                    y0 = fmaf(k4.x, wc.x, y0); y1 = fmaf(k4.x, wc.y, y1);
                    y2 = fmaf(k4.x, wc.z, y2); y3 = fmaf(k4.x, wc.w, y3);
                    y0 = fmaf(k4.y, wlq.w, y0); y1 = fmaf(k4.y, wc.x, y1);
                    y2 = fmaf(k4.y, wc.y, y2); y3 = fmaf(k4.y, wc.z, y3);
                    y0 = fmaf(k4.z, wlq.z, y0); y1 = fmaf(k4.z, wlq.w, y1);
                    y2 = fmaf(k4.z, wc.x, y2); y3 = fmaf(k4.z, wc.y, y3);
                    y0 = fmaf(k4.w, wlq.y, y0); y1 = fmaf(k4.w, wlq.z, y1);
                    y2 = fmaf(k4.w, wlq.w, y2); y3 = fmaf(k4.w, wc.x, y3);
                    wc = wlq;
                }

                y0 = fmaf(Dv, uo.x, y0); y1 = fmaf(Dv, uo.y, y1);
                y2 = fmaf(Dv, uo.z, y2); y3 = fmaf(Dv, uo.w, y3);
                y0 = 0.5f * y0 * (1.f + erff(y0 * is2));
                y1 = 0.5f * y1 * (1.f + erff(y1 * is2));
                y2 = 0.5f * y2 * (1.f + erff(y2 * is2));
                y3 = 0.5f * y3 * (1.f + erff(y3 * is2));
                if (rep == 0) { yA0 = y0; yA1 = y1; yA2 = y2; yA3 = y3; }
                else          { yB0 = y0; yB1 = y1; yB2 = y2; yB3 = y3; }
            }

            /* all u reads of both chunks complete before overwrite */
            __syncwarp();
            *(float4*)(uh + chunkA * Tc + t0) = make_float4(yA0, yA1, yA2, yA3);
            *(float4*)(uh + chunkB * Tc + t0) = make_float4(yB0, yB1, yB2, yB3);
        }
        __syncwarp();   /* u_s/wsS/KsW settled within warp before next head */
    }
    __syncthreads();

    /* ---- vectorized coalesced store ---- */
    {
        float4* ob4 = (float4*)(out + (size_t)b * Lseq * Hdim + h0);
        #pragma unroll
        for (int it = 0; it < 8; ++it) {
            int f  = it * 512 + tid;
            int l  = f >> 1;
            int hg = f & 1;
            const float* src = u_s + (hg * 4) * LPAD + l;
            float4 v;
            v.x = src[0];
            v.y = src[LPAD];
            v.z = src[2 * LPAD];
            v.w = src[3 * LPAD];
            ob4[(size_t)l * (Hdim / 4) + hg] = v;
        }
    }
}

extern "C" void kernel_launch(void* const* d_in, const int* in_sizes, int n_in,
                              void* d_out, int out_size)
{
    const float* u      = (const float*)d_in[0];
    const float* log_dt = (const float*)d_in[1];
    const float* B_re   = (const float*)d_in[2];
    const float* B_im   = (const float*)d_in[3];
    const float* C      = (const float*)d_in[4];
    const float* A_real = (const float*)d_in[5];
    const float* A_imag = (const float*)d_in[6];
    const float* D      = (const float*)d_in[7];
    float* out = (float*)d_out;

    cudaFuncSetAttribute(s4d_main, cudaFuncAttributeMaxDynamicSharedMemorySize,
                         SMEM_BYTES);

    s4d_precompute<<<Hdim / 8, 256>>>(log_dt, B_re, B_im, C, A_real, A_imag);

    dim3 grid(Hdim / HG, Bsz);   /* 64 x 16 = 1024 CTAs */
    s4d_main<<<grid, 512, SMEM_BYTES>>>(u, D, out);
}

// round 15
// speedup vs baseline: 1.0690x; 1.0690x over previous
#include <cuda_runtime.h>

#define Bsz   16
#define Lseq  2048
#define Hdim  512
#define N2    32
#define Tc    32
#define NC    (Lseq / Tc)   /* 64 chunks */
#define HG    8
#define LPAD  2052          /* per-head time-contiguous stride (mult of 4) */
#define NCW   8             /* chunks per warp within a stream */

/* ---- precomputed per-mode tables ---- */
__device__ float4 g_AB[Hdim][N2];        /* (dtA.re, dtA.im, dtB.re, dtB.im)      */
__device__ float2 g_Q0[Hdim][N2];        /* 2*C*dtA                               */
__device__ float2 g_AT[Hdim][N2];        /* dtA^32                                */
__device__ float2 g_AT8[Hdim][N2];       /* dtA^256 (8-chunk block aggregate)     */
__device__ float  g_Vr[Hdim][N2][Tc];    /* Re(dtA^t)                             */
__device__ float  g_Vin[Hdim][N2][Tc];   /* -Im(dtA^t)                            */
__device__ float  g_K[Hdim][Tc];         /* K[j] = 2*Re(sum_n C*dtB*dtA^j)        */

__device__ __forceinline__ float2 cmul(float2 a, float2 b) {
    return make_float2(fmaf(a.x, b.x, -a.y * b.y), fmaf(a.x, b.y, a.y * b.x));
}

/* one warp per head, 512 blocks: full SM spread.
   Vandermonde staged through padded smem -> fully coalesced 128B stores. */
__global__ void s4d_precompute(const float* __restrict__ log_dt,
                               const float* __restrict__ B_re,
                               const float* __restrict__ B_im,
                               const float* __restrict__ Cmat,
                               const float* __restrict__ A_real,
                               const float* __restrict__ A_imag)
{
    __shared__ float tvr[N2 * 33];       /* [n][t] staging, pad 33 */
    __shared__ float tvi[N2 * 33];
    __shared__ float tk [Tc * 33];       /* [j][n] tap transpose   */

    const int n   = threadIdx.x;         /* one mode per lane */
    const int h   = blockIdx.x;
    const int idx = h * N2 + n;

    float dt  = expf(log_dt[h]);
    float Are = -expf(A_real[idx]) - 1e-6f;
    float Aim = A_imag[idx];

    float2 num = make_float2(1.f + 0.5f * dt * Are, 0.5f * dt * Aim);
    float2 den = make_float2(1.f + 1e-6f - 0.5f * dt * Are, -0.5f * dt * Aim);
    float  inv = 1.f / (den.x * den.x + den.y * den.y);
    float2 dtA = make_float2((num.x * den.x + num.y * den.y) * inv,
                             (num.y * den.x - num.x * den.y) * inv);
    float2 Bc  = make_float2(dt * B_re[idx], dt * B_im[idx]);
    float2 dtB = make_float2((Bc.x * den.x + Bc.y * den.y) * inv,
                             (Bc.y * den.x - Bc.x * den.y) * inv);
    float  Cv  = Cmat[idx];

    g_AB[h][n] = make_float4(dtA.x, dtA.y, dtB.x, dtB.y);
    g_Q0[h][n] = make_float2(2.f * Cv * dtA.x, 2.f * Cv * dtA.y);

    /* dtA^32 / dtA^256 by squaring */
    float2 a = dtA;
    #pragma unroll
    for (int s = 0; s < 5; ++s) a = cmul(a, a);
    g_AT[h][n] = a;
    float2 a8 = a;
    #pragma unroll
    for (int s = 0; s < 3; ++s) a8 = cmul(a8, a8);
    g_AT8[h][n] = a8;

    /* Vandermonde planes -> smem staging (lane = mode, loop over t) */
    {
        float2 v = make_float2(1.f, 0.f);
        #pragma unroll 8
        for (int t = 0; t < Tc; ++t) {
            tvr[n * 33 + t] =  v.x;
            tvi[n * 33 + t] = -v.y;
            v = cmul(v, dtA);
        }
    }

    /* Toeplitz taps -> smem transpose (lane = mode, loop over j) */
    {
        float2 ck = make_float2(Cv * dtB.x, Cv * dtB.y);
        #pragma unroll 8
        for (int j = 0; j < Tc; ++j) {
            tk[j * 33 + n] = ck.x;
            ck = cmul(ck, dtA);
        }
    }
    __syncwarp();

    /* coalesced table writes: lane = t, loop over modes (128B per store) */
    #pragma unroll 8
    for (int m = 0; m < N2; ++m) {
        g_Vr [h][m][n] = tvr[m * 33 + n];
        g_Vin[h][m][n] = tvi[m * 33 + n];
    }

    /* tap reduction: lane = tap index j, sum over modes */
    {
        float s = 0.f;
        #pragma unroll 8
        for (int m = 0; m < N2; ++m) s += tk[n * 33 + m];
        g_K[h][n] = 2.f * s;
    }
}

/* chunk projections for 4 chunks (bases b0..b3), lane = mode. */
__device__ __forceinline__ void proj4(const float* __restrict__ b0,
                                      const float* __restrict__ b1,
                                      const float* __restrict__ b2,
                                      const float* __restrict__ b3,
                                      float axr, float axi, float2 dtB,
                                      float2& o0, float2& o1, float2& o2, float2& o3)
{
    float pr = dtB.x, pi = dtB.y;
    float w0r = 0, w0i = 0, w1r = 0, w1i = 0;
    float w2r = 0, w2i = 0, w3r = 0, w3i = 0;
    #pragma unroll 2
    for (int tg = Tc - 4; tg >= 0; tg -= 4) {
        float4 a0 = *(const float4*)(b0 + tg);
        float4 a1 = *(const float4*)(b1 + tg);
        float4 a2 = *(const float4*)(b2 + tg);
        float4 a3 = *(const float4*)(b3 + tg);
        w0r = fmaf(pr, a0.w, w0r); w0i = fmaf(pi, a0.w, w0i);
        w1r = fmaf(pr, a1.w, w1r); w1i = fmaf(pi, a1.w, w1i);
        w2r = fmaf(pr, a2.w, w2r); w2i = fmaf(pi, a2.w, w2i);
        w3r = fmaf(pr, a3.w, w3r); w3i = fmaf(pi, a3.w, w3i);
        { float t_ = fmaf(pr, axr, -pi * axi); pi = fmaf(pr, axi, pi * axr); pr = t_; }
        w0r = fmaf(pr, a0.z, w0r); w0i = fmaf(pi, a0.z, w0i);
        w1r = fmaf(pr, a1.z, w1r); w1i = fmaf(pi, a1.z, w1i);
        w2r = fmaf(pr, a2.z, w2r); w2i = fmaf(pi, a2.z, w2i);
        w3r = fmaf(pr, a3.z, w3r); w3i = fmaf(pi, a3.z, w3i);
        { float t_ = fmaf(pr, axr, -pi * axi); pi = fmaf(pr, axi, pi * axr); pr = t_; }
        w0r = fmaf(pr, a0.y, w0r); w0i = fmaf(pi, a0.y, w0i);
        w1r = fmaf(pr, a1.y, w1r); w1i = fmaf(pi, a1.y, w1i);
        w2r = fmaf(pr, a2.y, w2r); w2i = fmaf(pi, a2.y, w2i);
        w3r = fmaf(pr, a3.y, w3r); w3i = fmaf(pi, a3.y, w3i);
        { float t_ = fmaf(pr, axr, -pi * axi); pi = fmaf(pr, axi, pi * axr); pr = t_; }
        w0r = fmaf(pr, a0.x, w0r); w0i = fmaf(pi, a0.x, w0i);
        w1r = fmaf(pr, a1.x, w1r); w1i = fmaf(pi, a1.x, w1i);
        w2r = fmaf(pr, a2.x, w2r); w2i = fmaf(pi, a2.x, w2i);
        w3r = fmaf(pr, a3.x, w3r); w3i = fmaf(pi, a3.x, w3i);
        { float t_ = fmaf(pr, axr, -pi * axi); pi = fmaf(pr, axi, pi * axr); pr = t_; }
    }
    o0 = make_float2(w0r, w0i); o1 = make_float2(w1r, w1i);
    o2 = make_float2(w2r, w2i); o3 = make_float2(w3r, w3i);
}

/* smem: u 65664B + ws 32KB + bs (double-buffered, 2 streams) 8KB + Kw 2KB */
#define SMEM_BYTES (HG * LPAD * 4 + 2 * NC * N2 * 8 + 4 * NCW * N2 * 8 + 16 * Tc * 4)

#define STREAM_BAR(id) asm volatile("bar.sync %0, 256;" :: "r"(id) : "memory")

__global__ void __launch_bounds__(512, 2)
s4d_main(const float* __restrict__ u,
         const float* __restrict__ Dptr,
         float* __restrict__ out)
{
    extern __shared__ float sm[];
    float*  u_s = sm;                                   /* [hh][l], stride LPAD   */
    float2* ws  = (float2*)(sm + HG * LPAD);            /* [sid][chunk][mode] x'  */
    float2* bs  = ws + 2 * NC * N2;                     /* [sid][buf][wl][mode]   */
    float*  Kw  = (float*)(bs + 4 * NCW * N2);          /* [warp][32] taps        */

    const int b    = blockIdx.y;
    const int h0   = blockIdx.x * HG;
    const int tid  = threadIdx.x;
    const int warp = tid >> 5;
    const int lane = tid & 31;
    const int sid  = warp >> 3;       /* stream 0/1 */
    const int wl   = warp & 7;        /* warp within stream */
    const int barid = 1 + sid;
    const float Dv = *Dptr;

    float2* wsS = ws + sid * (NC * N2);
    float*  KsW = Kw + warp * Tc;

    /* ---- vectorized coalesced load -> per-head contiguous smem ---- */
    {
        const float4* ub4 = (const float4*)(u + (size_t)b * Lseq * Hdim + h0);
        #pragma unroll
        for (int it = 0; it < 8; ++it) {
            int f  = it * 512 + tid;          /* [0, 4096) */
            int l  = f >> 1;
            int hg = f & 1;
            float4 v = ub4[(size_t)l * (Hdim / 4) + hg];
            float* dst = u_s + (hg * 4) * LPAD + l;
            dst[0]        = v.x;
            dst[LPAD]     = v.y;
            dst[2 * LPAD] = v.z;
            dst[3 * LPAD] = v.w;
        }
    }
    __syncthreads();

    for (int ih = 0; ih < 4; ++ih) {
        const int hh = 2 * ih + sid;
        const int h  = h0 + hh;
        const float* uh = u_s + hh * LPAD;
        float2* bsB = bs + ((sid << 1) | (ih & 1)) * (NCW * N2);  /* dbl-buffered */

        KsW[lane] = g_K[h][lane];   /* per-warp taps; syncwarp before use below */

        /* ===== pass 1: 8 chunk projections per warp, kept in registers ===== */
        float4 ab = g_AB[h][lane];
        float2 dtB = make_float2(ab.z, ab.w);
        float2 w0, w1, w2, w3, w4, w5, w6, w7;
        {
            const float* cb = uh + (NCW * wl) * Tc;
            proj4(cb,          cb + Tc,     cb + 2 * Tc, cb + 3 * Tc,
                  ab.x, ab.y, dtB, w0, w1, w2, w3);
            proj4(cb + 4 * Tc, cb + 5 * Tc, cb + 6 * Tc, cb + 7 * Tc,
                  ab.x, ab.y, dtB, w4, w5, w6, w7);
        }

        /* ===== block aggregate S = sum AT^{7-j} w_j (Horner) -> bsB ===== */
        const float2 AT = g_AT[h][lane];
        {
            float sr = w0.x, si = w0.y;
            #define HSTEP(W) { float nr = fmaf(AT.x, sr, fmaf(-AT.y, si, (W).x)); \
                               float ni = fmaf(AT.x, si, fmaf( AT.y, sr, (W).y)); \
                               sr = nr; si = ni; }
            HSTEP(w1) HSTEP(w2) HSTEP(w3) HSTEP(w4) HSTEP(w5) HSTEP(w6) HSTEP(w7)
            #undef HSTEP
            bsB[wl * N2 + lane] = make_float2(sr, si);
        }
        STREAM_BAR(barid);   /* the ONLY cross-warp sync per head */

        /* ===== redundant per-warp scan of block aggregates + local expand ===== */
        {
            float2 A8 = g_AT8[h][lane];
            float2 Q0 = g_Q0[h][lane];
            float xr = 0.f, xi = 0.f, kr = 0.f, ki = 0.f;
            #pragma unroll
            for (int k = 0; k < NCW; ++k) {
                if (k == wl) { kr = xr; ki = xi; }   /* keep state entering own block */
                float2 S = bsB[k * N2 + lane];
                float nr = fmaf(A8.x, xr, fmaf(-A8.y, xi, S.x));
                float ni = fmaf(A8.x, xi, fmaf( A8.y, xr, S.y));
                xr = nr; xi = ni;
            }
            xr = kr; xi = ki;
            /* expand within own block; write x' = Q0 * x_entry (own warp range) */
            #define XSTEP(j, W) { \
                wsS[(NCW * wl + (j)) * N2 + lane] = \
                    make_float2(fmaf(Q0.x, xr, -Q0.y * xi), fmaf(Q0.x, xi, Q0.y * xr)); \
                float nr = fmaf(AT.x, xr, fmaf(-AT.y, xi, (W).x)); \
                float ni = fmaf(AT.x, xi, fmaf( AT.y, xr, (W).y)); \
                xr = nr; xi = ni; }
            XSTEP(0, w0) XSTEP(1, w1) XSTEP(2, w2) XSTEP(3, w3)
            XSTEP(4, w4) XSTEP(5, w5) XSTEP(6, w6) XSTEP(7, w7)
            #undef XSTEP
        }
        __syncwarp();   /* wsS + KsW writes visible across own warp's lanes */

        /* ===== pass 3: corr (V loaded once, 8 accumulators) + Toeplitz +
                 D*u + GELU.  lane = (cl, tb); chunks A = 8wl+cl, B = 8wl+4+cl ===== */
        {
            const int cl = lane >> 3, tb = lane & 7, t0 = tb << 2;
            const int chunkA = NCW * wl + cl;
            const int chunkB = NCW * wl + 4 + cl;

            float yA0 = 0.f, yA1 = 0.f, yA2 = 0.f, yA3 = 0.f;
            float yB0 = 0.f, yB1 = 0.f, yB2 = 0.f, yB3 = 0.f;

            /* --- inter-chunk correction: each V load feeds 8 accumulators --- */
            {
                const float4* Vr4 = (const float4*)&g_Vr [h][0][0];
                const float4* Vi4 = (const float4*)&g_Vin[h][0][0];
                const float4* xs4 = (const float4*)wsS;
                const int xbA = chunkA * (N2 / 2);
                const int xbB = chunkB * (N2 / 2);
                #pragma unroll 4
                for (int n2 = 0; n2 < N2; n2 += 2) {
                    float4 vr0 = Vr4[ n2      * 8 + tb];
                    float4 vi0 = Vi4[ n2      * 8 + tb];
                    float4 vr1 = Vr4[(n2 + 1) * 8 + tb];
                    float4 vi1 = Vi4[(n2 + 1) * 8 + tb];
                    float4 xa  = xs4[xbA + (n2 >> 1)];
                    float4 xb  = xs4[xbB + (n2 >> 1)];

                    yA0 = fmaf(xa.x, vr0.x, yA0); yA0 = fmaf(xa.y, vi0.x, yA0);
                    yA1 = fmaf(xa.x, vr0.y, yA1); yA1 = fmaf(xa.y, vi0.y, yA1);
                    yA2 = fmaf(xa.x, vr0.z, yA2); yA2 = fmaf(xa.y, vi0.z, yA2);
                    yA3 = fmaf(xa.x, vr0.w, yA3); yA3 = fmaf(xa.y, vi0.w, yA3);
                    yA0 = fmaf(xa.z, vr1.x, yA0); yA0 = fmaf(xa.w, vi1.x, yA0);
                    yA1 = fmaf(xa.z, vr1.y, yA1); yA1 = fmaf(xa.w, vi1.y, yA1);
                    yA2 = fmaf(xa.z, vr1.z, yA2); yA2 = fmaf(xa.w, vi1.z, yA2);
                    yA3 = fmaf(xa.z, vr1.w, yA3); yA3 = fmaf(xa.w, vi1.w, yA3);

                    yB0 = fmaf(xb.x, vr0.x, yB0); yB0 = fmaf(xb.y, vi0.x, yB0);
                    yB1 = fmaf(xb.x, vr0.y, yB1); yB1 = fmaf(xb.y, vi0.y, yB1);
                    yB2 = fmaf(xb.x, vr0.z, yB2); yB2 = fmaf(xb.y, vi0.z, yB2);
                    yB3 = fmaf(xb.x, vr0.w, yB3); yB3 = fmaf(xb.y, vi0.w, yB3);
                    yB0 = fmaf(xb.z, vr1.x, yB0); yB0 = fmaf(xb.w, vi1.x, yB0);
                    yB1 = fmaf(xb.z, vr1.y, yB1); yB1 = fmaf(xb.w, vi1.y, yB1);
                    yB2 = fmaf(xb.z, vr1.z, yB2); yB2 = fmaf(xb.w, vi1.z, yB2);
                    yB3 = fmaf(xb.z, vr1.w, yB3); yB3 = fmaf(xb.w, vi1.w, yB3);
                }
            }

            /* --- intra-chunk Toeplitz + epilogue, per rep (sequential) --- */
            const float4* Ks4 = (const float4*)KsW;
            const float is2 = 0.70710678118654752440f;

            #pragma unroll
            for (int rep = 0; rep < 2; ++rep) {
                const int chunk = (rep == 0) ? chunkA : chunkB;
                const float* uc = uh + chunk * Tc;
                float y0 = (rep == 0) ? yA0 : yB0;
                float y1 = (rep == 0) ? yA1 : yB1;
                float y2 = (rep == 0) ? yA2 : yB2;
                float y3 = (rep == 0) ? yA3 : yB3;

                float4 wc = *(const float4*)(uc + t0);
                const float4 uo = wc;
                #pragma unroll
                for (int jb = 0; jb < Tc; jb += 4) {
                    const int idx = t0 - jb - 4;
                    float4 wlq;
                    if (idx >= 0) wlq = *(const float4*)(uc + idx);
                    else          wlq = make_float4(0.f, 0.f, 0.f, 0.f);
                    float4 k4 = Ks4[jb >> 2];
                    y0 = fmaf(k4.x, wc.x, y0); y1 = fmaf(k4.x, wc.y, y1);
                    y2 = fmaf(k4.x, wc.z, y2); y3 = fmaf(k4.x, wc.w, y3);
                    y0 = fmaf(k4.y, wlq.w, y0); y1 = fmaf(k4.y, wc.x, y1);
                    y2 = fmaf(k4.y, wc.y, y2); y3 = fmaf(k4.y, wc.z, y3);
                    y0 = fmaf(k4.z, wlq.z, y0); y1 = fmaf(k4.z, wlq.w, y1);
                    y2 = fmaf(k4.z, wc.x, y2); y3 = fmaf(k4.z, wc.y, y3);
                    y0 = fmaf(k4.w, wlq.y, y0); y1 = fmaf(k4.w, wlq.z, y1);
                    y2 = fmaf(k4.w, wlq.w, y2); y3 = fmaf(k4.w, wc.x, y3);
                    wc = wlq;
                }

                y0 = fmaf(Dv, uo.x, y0); y1 = fmaf(Dv, uo.y, y1);
                y2 = fmaf(Dv, uo.z, y2); y3 = fmaf(Dv, uo.w, y3);
                y0 = 0.5f * y0 * (1.f + erff(y0 * is2));
                y1 = 0.5f * y1 * (1.f + erff(y1 * is2));
                y2 = 0.5f * y2 * (1.f + erff(y2 * is2));
                y3 = 0.5f * y3 * (1.f + erff(y3 * is2));
                if (rep == 0) { yA0 = y0; yA1 = y1; yA2 = y2; yA3 = y3; }
                else          { yB0 = y0; yB1 = y1; yB2 = y2; yB3 = y3; }
            }

            /* all u reads of both chunks complete before overwrite */
            __syncwarp();
            *(float4*)(uh + chunkA * Tc + t0) = make_float4(yA0, yA1, yA2, yA3);
            *(float4*)(uh + chunkB * Tc + t0) = make_float4(yB0, yB1, yB2, yB3);
        }
        __syncwarp();   /* u_s/wsS/KsW settled within warp before next head */
    }
    __syncthreads();

    /* ---- vectorized coalesced store ---- */
    {
        float4* ob4 = (float4*)(out + (size_t)b * Lseq * Hdim + h0);
        #pragma unroll
        for (int it = 0; it < 8; ++it) {
            int f  = it * 512 + tid;
            int l  = f >> 1;
            int hg = f & 1;
            const float* src = u_s + (hg * 4) * LPAD + l;
            float4 v;
            v.x = src[0];
            v.y = src[LPAD];
            v.z = src[2 * LPAD];
            v.w = src[3 * LPAD];
            ob4[(size_t)l * (Hdim / 4) + hg] = v;
        }
    }
}

extern "C" void kernel_launch(void* const* d_in, const int* in_sizes, int n_in,
                              void* d_out, int out_size)
{
    const float* u      = (const float*)d_in[0];
    const float* log_dt = (const float*)d_in[1];
    const float* B_re   = (const float*)d_in[2];
    const float* B_im   = (const float*)d_in[3];
    const float* C      = (const float*)d_in[4];
    const float* A_real = (const float*)d_in[5];
    const float* A_imag = (const float*)d_in[6];
    const float* D      = (const float*)d_in[7];
    float* out = (float*)d_out;

    cudaFuncSetAttribute(s4d_main, cudaFuncAttributeMaxDynamicSharedMemorySize,
                         SMEM_BYTES);

    s4d_precompute<<<Hdim, N2>>>(log_dt, B_re, B_im, C, A_real, A_imag);

    dim3 grid(Hdim / HG, Bsz);   /* 64 x 16 = 1024 CTAs */
    s4d_main<<<grid, 512, SMEM_BYTES>>>(u, D, out);
}

// round 16
// speedup vs baseline: 1.0711x; 1.0019x over previous
#include <cuda_runtime.h>

#define Bsz   16
#define Lseq  2048
#define Hdim  512
#define N2    32
#define Tc    32
#define NC    (Lseq / Tc)   /* 64 chunks */
#define HG    8
#define LPAD  2052          /* per-head time-contiguous stride (mult of 4) */
#define NCW   8             /* chunks per warp within a stream */

/* ---- precomputed per-mode tables ---- */
__device__ float4 g_AB[Hdim][N2];        /* (dtA.re, dtA.im, dtB.re, dtB.im)      */
__device__ float2 g_Q0[Hdim][N2];        /* 2*C*dtA                               */
__device__ float2 g_AT[Hdim][N2];        /* dtA^32                                */
__device__ float2 g_AT8[Hdim][N2];       /* dtA^256 (8-chunk block aggregate)     */
__device__ float  g_Vr[Hdim][N2][Tc];    /* Re(dtA^t)                             */
__device__ float  g_Vin[Hdim][N2][Tc];   /* -Im(dtA^t)                            */
__device__ float  g_K[Hdim][Tc];         /* K[j] = 2*Re(sum_n C*dtB*dtA^j)        */

__device__ __forceinline__ float2 cmul(float2 a, float2 b) {
    return make_float2(fmaf(a.x, b.x, -a.y * b.y), fmaf(a.x, b.y, a.y * b.x));
}

/* exact-GELU via A&S 26.2.17 erf (|eps| <= 1.5e-7 abs): ~8 FMA + 2 MUFU */
__device__ __forceinline__ float gelu_fast(float y) {
    const float is2 = 0.70710678118654752440f;
    float x  = y * is2;
    float ax = fabsf(x);
    float t  = __fdividef(1.0f, fmaf(0.3275911f, ax, 1.0f));
    float p  = fmaf(t, 1.061405429f, -1.453152027f);
    p = fmaf(t, p,  1.421413741f);
    p = fmaf(t, p, -0.284496736f);
    p = fmaf(t, p,  0.254829592f);
    float e  = __expf(-ax * ax);
    float er = fmaf(-p * t, e, 1.0f);          /* erf(|x|) */
    er = copysignf(er, x);
    return 0.5f * y * (1.0f + er);
}

/* one warp per head, 512 blocks: full SM spread.
   Vandermonde staged through padded smem -> fully coalesced 128B stores. */
__global__ void s4d_precompute(const float* __restrict__ log_dt,
                               const float* __restrict__ B_re,
                               const float* __restrict__ B_im,
                               const float* __restrict__ Cmat,
                               const float* __restrict__ A_real,
                               const float* __restrict__ A_imag)
{
    __shared__ float tvr[N2 * 33];       /* [n][t] staging, pad 33 */
    __shared__ float tvi[N2 * 33];
    __shared__ float tk [Tc * 33];       /* [j][n] tap transpose   */

    const int n   = threadIdx.x;         /* one mode per lane */
    const int h   = blockIdx.x;
    const int idx = h * N2 + n;

    float dt  = expf(log_dt[h]);
    float Are = -expf(A_real[idx]) - 1e-6f;
    float Aim = A_imag[idx];

    float2 num = make_float2(1.f + 0.5f * dt * Are, 0.5f * dt * Aim);
    float2 den = make_float2(1.f + 1e-6f - 0.5f * dt * Are, -0.5f * dt * Aim);
    float  inv = 1.f / (den.x * den.x + den.y * den.y);
    float2 dtA = make_float2((num.x * den.x + num.y * den.y) * inv,
                             (num.y * den.x - num.x * den.y) * inv);
    float2 Bc  = make_float2(dt * B_re[idx], dt * B_im[idx]);
    float2 dtB = make_float2((Bc.x * den.x + Bc.y * den.y) * inv,
                             (Bc.y * den.x - Bc.x * den.y) * inv);
    float  Cv  = Cmat[idx];

    g_AB[h][n] = make_float4(dtA.x, dtA.y, dtB.x, dtB.y);
    g_Q0[h][n] = make_float2(2.f * Cv * dtA.x, 2.f * Cv * dtA.y);

    /* dtA^32 / dtA^256 by squaring */
    float2 a = dtA;
    #pragma unroll
    for (int s = 0; s < 5; ++s) a = cmul(a, a);
    g_AT[h][n] = a;
    float2 a8 = a;
    #pragma unroll
    for (int s = 0; s < 3; ++s) a8 = cmul(a8, a8);
    g_AT8[h][n] = a8;

    /* Vandermonde planes -> smem staging (lane = mode, loop over t) */
    {
        float2 v = make_float2(1.f, 0.f);
        #pragma unroll 8
        for (int t = 0; t < Tc; ++t) {
            tvr[n * 33 + t] =  v.x;
            tvi[n * 33 + t] = -v.y;
            v = cmul(v, dtA);
        }
    }

    /* Toeplitz taps -> smem transpose (lane = mode, loop over j) */
    {
        float2 ck = make_float2(Cv * dtB.x, Cv * dtB.y);
        #pragma unroll 8
        for (int j = 0; j < Tc; ++j) {
            tk[j * 33 + n] = ck.x;
            ck = cmul(ck, dtA);
        }
    }
    __syncwarp();

    /* coalesced table writes: lane = t, loop over modes (128B per store) */
    #pragma unroll 8
    for (int m = 0; m < N2; ++m) {
        g_Vr [h][m][n] = tvr[m * 33 + n];
        g_Vin[h][m][n] = tvi[m * 33 + n];
    }

    /* tap reduction: lane = tap index j, sum over modes */
    {
        float s = 0.f;
        #pragma unroll 8
        for (int m = 0; m < N2; ++m) s += tk[n * 33 + m];
        g_K[h][n] = 2.f * s;
    }
}

/* chunk projections for 4 chunks (bases b0..b3), lane = mode. */
__device__ __forceinline__ void proj4(const float* __restrict__ b0,
                                      const float* __restrict__ b1,
                                      const float* __restrict__ b2,
                                      const float* __restrict__ b3,
                                      float axr, float axi, float2 dtB,
                                      float2& o0, float2& o1, float2& o2, float2& o3)
{
    float pr = dtB.x, pi = dtB.y;
    float w0r = 0, w0i = 0, w1r = 0, w1i = 0;
    float w2r = 0, w2i = 0, w3r = 0, w3i = 0;
    #pragma unroll 2
    for (int tg = Tc - 4; tg >= 0; tg -= 4) {
        float4 a0 = *(const float4*)(b0 + tg);
        float4 a1 = *(const float4*)(b1 + tg);
        float4 a2 = *(const float4*)(b2 + tg);
        float4 a3 = *(const float4*)(b3 + tg);
        w0r = fmaf(pr, a0.w, w0r); w0i = fmaf(pi, a0.w, w0i);
        w1r = fmaf(pr, a1.w, w1r); w1i = fmaf(pi, a1.w, w1i);
        w2r = fmaf(pr, a2.w, w2r); w2i = fmaf(pi, a2.w, w2i);
        w3r = fmaf(pr, a3.w, w3r); w3i = fmaf(pi, a3.w, w3i);
        { float t_ = fmaf(pr, axr, -pi * axi); pi = fmaf(pr, axi, pi * axr); pr = t_; }
        w0r = fmaf(pr, a0.z, w0r); w0i = fmaf(pi, a0.z, w0i);
        w1r = fmaf(pr, a1.z, w1r); w1i = fmaf(pi, a1.z, w1i);
        w2r = fmaf(pr, a2.z, w2r); w2i = fmaf(pi, a2.z, w2i);
        w3r = fmaf(pr, a3.z, w3r); w3i = fmaf(pi, a3.z, w3i);
        { float t_ = fmaf(pr, axr, -pi * axi); pi = fmaf(pr, axi, pi * axr); pr = t_; }
        w0r = fmaf(pr, a0.y, w0r); w0i = fmaf(pi, a0.y, w0i);
        w1r = fmaf(pr, a1.y, w1r); w1i = fmaf(pi, a1.y, w1i);
        w2r = fmaf(pr, a2.y, w2r); w2i = fmaf(pi, a2.y, w2i);
        w3r = fmaf(pr, a3.y, w3r); w3i = fmaf(pi, a3.y, w3i);
        { float t_ = fmaf(pr, axr, -pi * axi); pi = fmaf(pr, axi, pi * axr); pr = t_; }
        w0r = fmaf(pr, a0.x, w0r); w0i = fmaf(pi, a0.x, w0i);
        w1r = fmaf(pr, a1.x, w1r); w1i = fmaf(pi, a1.x, w1i);
        w2r = fmaf(pr, a2.x, w2r); w2i = fmaf(pi, a2.x, w2i);
        w3r = fmaf(pr, a3.x, w3r); w3i = fmaf(pi, a3.x, w3i);
        { float t_ = fmaf(pr, axr, -pi * axi); pi = fmaf(pr, axi, pi * axr); pr = t_; }
    }
    o0 = make_float2(w0r, w0i); o1 = make_float2(w1r, w1i);
    o2 = make_float2(w2r, w2i); o3 = make_float2(w3r, w3i);
}

/* smem: u 65664B + ws 32KB + bs (double-buffered, 2 streams) 8KB + Kw 2KB */
#define SMEM_BYTES (HG * LPAD * 4 + 2 * NC * N2 * 8 + 4 * NCW * N2 * 8 + 16 * Tc * 4)

#define STREAM_BAR(id) asm volatile("bar.sync %0, 256;" :: "r"(id) : "memory")

__global__ void __launch_bounds__(512, 2)
s4d_main(const float* __restrict__ u,
         const float* __restrict__ Dptr,
         float* __restrict__ out)
{
    extern __shared__ float sm[];
    float*  u_s = sm;                                   /* [hh][l], stride LPAD   */
    float2* ws  = (float2*)(sm + HG * LPAD);            /* [sid][chunk][mode] x'  */
    float2* bs  = ws + 2 * NC * N2;                     /* [sid][buf][wl][mode]   */
    float*  Kw  = (float*)(bs + 4 * NCW * N2);          /* [warp][32] taps        */

    const int b    = blockIdx.y;
    const int h0   = blockIdx.x * HG;
    const int tid  = threadIdx.x;
    const int warp = tid >> 5;
    const int lane = tid & 31;
    const int sid  = warp >> 3;       /* stream 0/1 */
    const int wl   = warp & 7;        /* warp within stream */
    const int barid = 1 + sid;
    const float Dv = *Dptr;

    float2* wsS = ws + sid * (NC * N2);
    float*  KsW = Kw + warp * Tc;

    /* ---- vectorized coalesced load -> per-head contiguous smem ---- */
    {
        const float4* ub4 = (const float4*)(u + (size_t)b * Lseq * Hdim + h0);
        #pragma unroll
        for (int it = 0; it < 8; ++it) {
            int f  = it * 512 + tid;          /* [0, 4096) */
            int l  = f >> 1;
            int hg = f & 1;
            float4 v = ub4[(size_t)l * (Hdim / 4) + hg];
            float* dst = u_s + (hg * 4) * LPAD + l;
            dst[0]        = v.x;
            dst[LPAD]     = v.y;
            dst[2 * LPAD] = v.z;
            dst[3 * LPAD] = v.w;
        }
    }
    __syncthreads();

    for (int ih = 0; ih < 4; ++ih) {
        const int hh = 2 * ih + sid;
        const int h  = h0 + hh;
        const float* uh = u_s + hh * LPAD;
        float2* bsB = bs + ((sid << 1) | (ih & 1)) * (NCW * N2);  /* dbl-buffered */

        KsW[lane] = g_K[h][lane];   /* per-warp taps; syncwarp before use below */

        /* ===== pass 1: 8 chunk projections per warp, kept in registers ===== */
        float4 ab = g_AB[h][lane];
        float2 dtB = make_float2(ab.z, ab.w);
        float2 w0, w1, w2, w3, w4, w5, w6, w7;
        {
            const float* cb = uh + (NCW * wl) * Tc;
            proj4(cb,          cb + Tc,     cb + 2 * Tc, cb + 3 * Tc,
                  ab.x, ab.y, dtB, w0, w1, w2, w3);
            proj4(cb + 4 * Tc, cb + 5 * Tc, cb + 6 * Tc, cb + 7 * Tc,
                  ab.x, ab.y, dtB, w4, w5, w6, w7);
        }

        /* ===== block aggregate S = sum AT^{7-j} w_j (Horner) -> bsB ===== */
        const float2 AT = g_AT[h][lane];
        {
            float sr = w0.x, si = w0.y;
            #define HSTEP(W) { float nr = fmaf(AT.x, sr, fmaf(-AT.y, si, (W).x)); \
                               float ni = fmaf(AT.x, si, fmaf( AT.y, sr, (W).y)); \
                               sr = nr; si = ni; }
            HSTEP(w1) HSTEP(w2) HSTEP(w3) HSTEP(w4) HSTEP(w5) HSTEP(w6) HSTEP(w7)
            #undef HSTEP
            bsB[wl * N2 + lane] = make_float2(sr, si);
        }
        STREAM_BAR(barid);   /* the ONLY cross-warp sync per head */

        /* ===== redundant per-warp scan of block aggregates + local expand ===== */
        {
            float2 A8 = g_AT8[h][lane];
            float2 Q0 = g_Q0[h][lane];
            float xr = 0.f, xi = 0.f, kr = 0.f, ki = 0.f;
            #pragma unroll
            for (int k = 0; k < NCW; ++k) {
                if (k == wl) { kr = xr; ki = xi; }   /* keep state entering own block */
                float2 S = bsB[k * N2 + lane];
                float nr = fmaf(A8.x, xr, fmaf(-A8.y, xi, S.x));
                float ni = fmaf(A8.x, xi, fmaf( A8.y, xr, S.y));
                xr = nr; xi = ni;
            }
            xr = kr; xi = ki;
            /* expand within own block; write x' = Q0 * x_entry (own warp range) */
            #define XSTEP(j, W) { \
                wsS[(NCW * wl + (j)) * N2 + lane] = \
                    make_float2(fmaf(Q0.x, xr, -Q0.y * xi), fmaf(Q0.x, xi, Q0.y * xr)); \
                float nr = fmaf(AT.x, xr, fmaf(-AT.y, xi, (W).x)); \
                float ni = fmaf(AT.x, xi, fmaf( AT.y, xr, (W).y)); \
                xr = nr; xi = ni; }
            XSTEP(0, w0) XSTEP(1, w1) XSTEP(2, w2) XSTEP(3, w3)
            XSTEP(4, w4) XSTEP(5, w5) XSTEP(6, w6) XSTEP(7, w7)
            #undef XSTEP
        }
        __syncwarp();   /* wsS + KsW writes visible across own warp's lanes */

        /* ===== pass 3: corr (V loaded once, 8 accumulators) + Toeplitz +
                 D*u + GELU.  lane = (cl, tb); chunks A = 8wl+cl, B = 8wl+4+cl ===== */
        {
            const int cl = lane >> 3, tb = lane & 7, t0 = tb << 2;
            const int chunkA = NCW * wl + cl;
            const int chunkB = NCW * wl + 4 + cl;

            float yA0 = 0.f, yA1 = 0.f, yA2 = 0.f, yA3 = 0.f;
            float yB0 = 0.f, yB1 = 0.f, yB2 = 0.f, yB3 = 0.f;

            /* --- inter-chunk correction: each V load feeds 8 accumulators --- */
            {
                const float4* Vr4 = (const float4*)&g_Vr [h][0][0];
                const float4* Vi4 = (const float4*)&g_Vin[h][0][0];
                const float4* xs4 = (const float4*)wsS;
                const int xbA = chunkA * (N2 / 2);
                const int xbB = chunkB * (N2 / 2);
                #pragma unroll 4
                for (int n2 = 0; n2 < N2; n2 += 2) {
                    float4 vr0 = Vr4[ n2      * 8 + tb];
                    float4 vi0 = Vi4[ n2      * 8 + tb];
                    float4 vr1 = Vr4[(n2 + 1) * 8 + tb];
                    float4 vi1 = Vi4[(n2 + 1) * 8 + tb];
                    float4 xa  = xs4[xbA + (n2 >> 1)];
                    float4 xb  = xs4[xbB + (n2 >> 1)];

                    yA0 = fmaf(xa.x, vr0.x, yA0); yA0 = fmaf(xa.y, vi0.x, yA0);
                    yA1 = fmaf(xa.x, vr0.y, yA1); yA1 = fmaf(xa.y, vi0.y, yA1);
                    yA2 = fmaf(xa.x, vr0.z, yA2); yA2 = fmaf(xa.y, vi0.z, yA2);
                    yA3 = fmaf(xa.x, vr0.w, yA3); yA3 = fmaf(xa.y, vi0.w, yA3);
                    yA0 = fmaf(xa.z, vr1.x, yA0); yA0 = fmaf(xa.w, vi1.x, yA0);
                    yA1 = fmaf(xa.z, vr1.y, yA1); yA1 = fmaf(xa.w, vi1.y, yA1);
                    yA2 = fmaf(xa.z, vr1.z, yA2); yA2 = fmaf(xa.w, vi1.z, yA2);
                    yA3 = fmaf(xa.z, vr1.w, yA3); yA3 = fmaf(xa.w, vi1.w, yA3);

                    yB0 = fmaf(xb.x, vr0.x, yB0); yB0 = fmaf(xb.y, vi0.x, yB0);
                    yB1 = fmaf(xb.x, vr0.y, yB1); yB1 = fmaf(xb.y, vi0.y, yB1);
                    yB2 = fmaf(xb.x, vr0.z, yB2); yB2 = fmaf(xb.y, vi0.z, yB2);
                    yB3 = fmaf(xb.x, vr0.w, yB3); yB3 = fmaf(xb.y, vi0.w, yB3);
                    yB0 = fmaf(xb.z, vr1.x, yB0); yB0 = fmaf(xb.w, vi1.x, yB0);
                    yB1 = fmaf(xb.z, vr1.y, yB1); yB1 = fmaf(xb.w, vi1.y, yB1);
                    yB2 = fmaf(xb.z, vr1.z, yB2); yB2 = fmaf(xb.w, vi1.z, yB2);
                    yB3 = fmaf(xb.z, vr1.w, yB3); yB3 = fmaf(xb.w, vi1.w, yB3);
                }
            }

            /* --- intra-chunk Toeplitz + epilogue, per rep (sequential) --- */
            const float4* Ks4 = (const float4*)KsW;

            #pragma unroll
            for (int rep = 0; rep < 2; ++rep) {
                const int chunk = (rep == 0) ? chunkA : chunkB;
                const float* uc = uh + chunk * Tc;
                float y0 = (rep == 0) ? yA0 : yB0;
                float y1 = (rep == 0) ? yA1 : yB1;
                float y2 = (rep == 0) ? yA2 : yB2;
                float y3 = (rep == 0) ? yA3 : yB3;

                float4 wc = *(const float4*)(uc + t0);
                const float4 uo = wc;
                #pragma unroll
                for (int jb = 0; jb < Tc; jb += 4) {
                    const int idx = t0 - jb - 4;
                    float4 wlq;
                    if (idx >= 0) wlq = *(const float4*)(uc + idx);
                    else          wlq = make_float4(0.f, 0.f, 0.f, 0.f);
                    float4 k4 = Ks4[jb >> 2];
                    y0 = fmaf(k4.x, wc.x, y0); y1 = fmaf(k4.x, wc.y, y1);
                    y2 = fmaf(k4.x, wc.z, y2); y3 = fmaf(k4.x, wc.w, y3);
                    y0 = fmaf(k4.y, wlq.w, y0); y1 = fmaf(k4.y, wc.x, y1);
                    y2 = fmaf(k4.y, wc.y, y2); y3 = fmaf(k4.y, wc.z, y3);
                    y0 = fmaf(k4.z, wlq.z, y0); y1 = fmaf(k4.z, wlq.w, y1);
                    y2 = fmaf(k4.z, wc.x, y2); y3 = fmaf(k4.z, wc.y, y3);
                    y0 = fmaf(k4.w, wlq.y, y0); y1 = fmaf(k4.w, wlq.z, y1);
                    y2 = fmaf(k4.w, wlq.w, y2); y3 = fmaf(k4.w, wc.x, y3);
                    wc = wlq;
                }

                y0 = fmaf(Dv, uo.x, y0); y1 = fmaf(Dv, uo.y, y1);
                y2 = fmaf(Dv, uo.z, y2); y3 = fmaf(Dv, uo.w, y3);
                y0 = gelu_fast(y0);
                y1 = gelu_fast(y1);
                y2 = gelu_fast(y2);
                y3 = gelu_fast(y3);
                if (rep == 0) { yA0 = y0; yA1 = y1; yA2 = y2; yA3 = y3; }
                else          { yB0 = y0; yB1 = y1; yB2 = y2; yB3 = y3; }
            }

            /* all u reads of both chunks complete before overwrite */
            __syncwarp();
            *(float4*)(uh + chunkA * Tc + t0) = make_float4(yA0, yA1, yA2, yA3);
            *(float4*)(uh + chunkB * Tc + t0) = make_float4(yB0, yB1, yB2, yB3);
        }
        __syncwarp();   /* u_s/wsS/KsW settled within warp before next head */
    }
    __syncthreads();

    /* ---- vectorized coalesced store ---- */
    {
        float4* ob4 = (float4*)(out + (size_t)b * Lseq * Hdim + h0);
        #pragma unroll
        for (int it = 0; it < 8; ++it) {
            int f  = it * 512 + tid;
            int l  = f >> 1;
            int hg = f & 1;
            const float* src = u_s + (hg * 4) * LPAD + l;
            float4 v;
            v.x = src[0];
            v.y = src[LPAD];
            v.z = src[2 * LPAD];
            v.w = src[3 * LPAD];
            ob4[(size_t)l * (Hdim / 4) + hg] = v;
        }
    }
}

extern "C" void kernel_launch(void* const* d_in, const int* in_sizes, int n_in,
                              void* d_out, int out_size)
{
    const float* u      = (const float*)d_in[0];
    const float* log_dt = (const float*)d_in[1];
    const float* B_re   = (const float*)d_in[2];
    const float* B_im   = (const float*)d_in[3];
    const float* C      = (const float*)d_in[4];
    const float* A_real = (const float*)d_in[5];
    const float* A_imag = (const float*)d_in[6];
    const float* D      = (const float*)d_in[7];
    float* out = (float*)d_out;

    cudaFuncSetAttribute(s4d_main, cudaFuncAttributeMaxDynamicSharedMemorySize,
                         SMEM_BYTES);

    s4d_precompute<<<Hdim, N2>>>(log_dt, B_re, B_im, C, A_real, A_imag);

    dim3 grid(Hdim / HG, Bsz);   /* 64 x 16 = 1024 CTAs */
    s4d_main<<<grid, 512, SMEM_BYTES>>>(u, D, out);
}